// round 16
// baseline (speedup 1.0000x reference)
#include <cuda_runtime.h>
#include <math.h>

#define BB 32
#define LL 512
#define NN 1023
#define EE 126
#define NBLK 148
#define NTHR 256
#define RT 64
#define WPITCH 140
#define ATP 68
#define SMEM_BYTES ((256 * WPITCH + 256 * ATP) * 4)

// Scratch (device globals — no allocations allowed)
__device__ float g_duo[BB * NN * 256];   // [b][node][0:128 down | 128:256 up]
__device__ float g_leaf[BB * LL * 128];  // leaf input features
__device__ float g_WcT[256 * 128];       // WcT[j][i] = Wc[i][j]
__device__ float g_WdT[256 * 256];
__device__ float g_WgT[128 * 128];
__device__ unsigned g_count = 0;
__device__ unsigned g_sense = 0;

// ---------- f32x2 helpers ----------
__device__ __forceinline__ unsigned long long pk2(float lo, float hi) {
    unsigned long long r;
    asm("mov.b64 %0, {%1,%2};" : "=l"(r) : "f"(lo), "f"(hi));
    return r;
}
__device__ __forceinline__ void fma2(unsigned long long& d, unsigned long long a, unsigned long long b) {
    asm("fma.rn.f32x2 %0, %1, %2, %0;" : "+l"(d) : "l"(a), "l"(b));
}
__device__ __forceinline__ void unpk2(unsigned long long v, float& a, float& b) {
    asm("mov.b64 {%0,%1}, %2;" : "=f"(a), "=f"(b) : "l"(v));
}
__device__ __forceinline__ float tanh_fast(float x) {
    float e = __expf(2.0f * x);
    return 1.0f - __fdividef(2.0f, e + 1.0f);
}
__device__ __forceinline__ float sigmoid_fast(float x) {
    return __fdividef(1.0f, 1.0f + __expf(-x));
}

// ---------- grid barrier (sense-reversing; all 148 CTAs resident by construction) ----------
__device__ __forceinline__ void gridbar(unsigned& ls) {
    ls ^= 1u;
    __syncthreads();
    if (threadIdx.x == 0) {
        __threadfence();
        if (atomicAdd(&g_count, 1u) == NBLK - 1) {
            g_count = 0u;
            atomicExch(&g_sense, ls);
        } else {
            while (atomicAdd(&g_sense, 0u) != ls) __nanosleep(64);
            __threadfence();
        }
    }
    __syncthreads();
}

// ---------- W load into permuted GEMM smem layout ----------
__device__ __forceinline__ void load_w_gemm(float* swW, const float* __restrict__ WT,
                                            int Ntot, int colBase) {
    for (int i = threadIdx.x; i < 256 * 32; i += NTHR) {
        int k = i >> 5, c4 = i & 31;
        float4 v = *(const float4*)&WT[k * Ntot + colBase + c4 * 4];
        *(float4*)&swW[k * WPITCH + (c4 + (c4 >> 3)) * 4] = v;
    }
}

// ---------- one GEMM tile: 64 rows x 128 cols, K=256, W in smem, A^T in smem ----------
// Thread: 4 rows x 8 cols = 16 f32x2 accumulators.
// MODE 0: up d=8 (A from g_leaf); MODE 1: up (A concat children up); MODE 2: down (A duo row)
template <int MODE>
__device__ void gemm_tile(const float* swW, float* swAT, int rowBase, int logR, int off, int y,
                          const float* __restrict__ bias) {
    const int tid = threadIdx.x;
    const int Rm1 = (1 << logR) - 1;

    // stage A^T: swAT[k*ATP + r] = A[r][k]; lanes walk r (conflict-free STS)
    for (int i = tid; i < RT * 64; i += NTHR) {
        int r = i & 63;
        int kq = (i >> 6) << 2;      // 0,4,...,252
        int m = rowBase + r;
        int b = m >> logR, pi = m & Rm1;
        const float* abase;
        if (MODE == 0)      abase = g_leaf + (((b << 9) + (pi << 1)) << 7);
        else if (MODE == 1) abase = g_duo + (b * NN + 2 * (off + pi) + 1) * 256 + 128;
        else                abase = g_duo + (b * NN + (off + pi)) * 256;
        int extra = (MODE == 1) ? ((kq >> 7) << 7) : 0;
        float4 v = *(const float4*)(abase + kq + extra);
        swAT[(kq + 0) * ATP + r] = v.x;
        swAT[(kq + 1) * ATP + r] = v.y;
        swAT[(kq + 2) * ATP + r] = v.z;
        swAT[(kq + 3) * ATP + r] = v.w;
    }
    __syncthreads();

    const int cg = tid & 15;     // 8 cols each
    const int rg = tid >> 4;     // 0..15, 4 rows each
    const int p0 = ((2 * cg) + ((2 * cg) >> 3)) * 4;
    const int p1 = ((2 * cg + 1) + ((2 * cg + 1) >> 3)) * 4;
    const float* aP = swAT + rg * 4;

    unsigned long long acc[4][4];
#pragma unroll
    for (int r = 0; r < 4; r++)
#pragma unroll
        for (int c = 0; c < 4; c++) acc[r][c] = 0ULL;

#pragma unroll 4
    for (int k = 0; k < 256; k++) {
        float4 a = *(const float4*)(aP + k * ATP);
        ulonglong2 w0 = *(const ulonglong2*)(swW + k * WPITCH + p0);
        ulonglong2 w1 = *(const ulonglong2*)(swW + k * WPITCH + p1);
        unsigned long long q;
        q = pk2(a.x, a.x); fma2(acc[0][0], q, w0.x); fma2(acc[0][1], q, w0.y); fma2(acc[0][2], q, w1.x); fma2(acc[0][3], q, w1.y);
        q = pk2(a.y, a.y); fma2(acc[1][0], q, w0.x); fma2(acc[1][1], q, w0.y); fma2(acc[1][2], q, w1.x); fma2(acc[1][3], q, w1.y);
        q = pk2(a.z, a.z); fma2(acc[2][0], q, w0.x); fma2(acc[2][1], q, w0.y); fma2(acc[2][2], q, w1.x); fma2(acc[2][3], q, w1.y);
        q = pk2(a.w, a.w); fma2(acc[3][0], q, w0.x); fma2(acc[3][1], q, w0.y); fma2(acc[3][2], q, w1.x); fma2(acc[3][3], q, w1.y);
    }
    __syncthreads();   // last swAT read done; safe for next tile's staging

    // epilogue
    const int colBase = (MODE == 2) ? (y << 7) : 0;
    float bcol[8];
#pragma unroll
    for (int j = 0; j < 8; j++) bcol[j] = bias[colBase + cg * 8 + j];
#pragma unroll
    for (int r = 0; r < 4; r++) {
        int m = rowBase + rg * 4 + r;
        int b = m >> logR, pi = m & Rm1;
        float* dst;
        if (MODE == 2) dst = g_duo + (b * NN + 2 * (off + pi) + 1 + y) * 256;
        else           dst = g_duo + (b * NN + (off + pi)) * 256 + 128;
        float o[8];
#pragma unroll
        for (int c2 = 0; c2 < 4; c2++) {
            float v0, v1;
            unpk2(acc[r][c2], v0, v1);
            o[2 * c2]     = tanh_fast(v0 + bcol[2 * c2]);
            o[2 * c2 + 1] = tanh_fast(v1 + bcol[2 * c2 + 1]);
        }
        *(float4*)&dst[cg * 8]     = make_float4(o[0], o[1], o[2], o[3]);
        *(float4*)&dst[cg * 8 + 4] = make_float4(o[4], o[5], o[6], o[7]);
    }
}

template <int MODE>
__device__ void level_gemm(const float* swW, float* swAT, const float* __restrict__ bias,
                           int logR, int off, int y) {
    int mt0, stride;
    if (MODE == 2) { mt0 = blockIdx.x >> 1; stride = NBLK / 2; }
    else           { mt0 = blockIdx.x;      stride = NBLK; }
    int nmt = (BB << logR) / RT;
    for (int mt = mt0; mt < nmt; mt += stride)
        gemm_tile<MODE>(swW, swAT, mt * RT, logR, off, y, bias);
}

// ---------- top of tree: up 3..0, gate, down 0..2 (one batch per block) ----------
// su/sd live in the (dead) swAT region.
__device__ void top_tree(float* swW, float* su, float* sd, int b,
                         const float* __restrict__ bc,
                         const float* __restrict__ bd, const float* __restrict__ bg) {
    int tid = threadIdx.x;
    float* duoB = g_duo + (long long)b * NN * 256;

    for (int idx = tid; idx < 16 * 128; idx += NTHR) {
        int n = 15 + (idx >> 7), c = idx & 127;
        su[n * 128 + c] = duoB[n * 256 + 128 + c];
    }
    __syncthreads();

    // upward levels 3..0 — WcT already in swW (permuted layout)
    for (int k = 3; k >= 0; --k) {
        int p0 = (1 << k) - 1, P = 1 << k;
        int col = tid & 127;
        int wcol = col + 4 * (col >> 5);
        for (int pi = tid >> 7; pi < P; pi += 2) {
            int p = p0 + pi;
            const float* ctx = &su[(2 * p + 1) * 128];
            float a0 = bc[col], a1 = 0.f, a2 = 0.f, a3 = 0.f;
#pragma unroll 8
            for (int j = 0; j < 256; j += 4) {
                a0 = fmaf(ctx[j + 0], swW[(j + 0) * WPITCH + wcol], a0);
                a1 = fmaf(ctx[j + 1], swW[(j + 1) * WPITCH + wcol], a1);
                a2 = fmaf(ctx[j + 2], swW[(j + 2) * WPITCH + wcol], a2);
                a3 = fmaf(ctx[j + 3], swW[(j + 3) * WPITCH + wcol], a3);
            }
            float v = tanh_fast((a0 + a1) + (a2 + a3));
            su[p * 128 + col] = v;
            duoB[p * 256 + 128 + col] = v;
        }
        __syncthreads();
    }

    // stage WgT linear (overwrite W area)
    for (int i = tid; i < 16384 / 4; i += NTHR)
        ((float4*)swW)[i] = ((const float4*)g_WgT)[i];
    __syncthreads();

    // root gate
    if (tid < 128) {
        int col = tid;
        float a0 = bg[col], a1 = 0.f, a2 = 0.f, a3 = 0.f;
#pragma unroll 8
        for (int j = 0; j < 128; j += 4) {
            a0 = fmaf(su[j + 0], swW[(j + 0) * 128 + col], a0);
            a1 = fmaf(su[j + 1], swW[(j + 1) * 128 + col], a1);
            a2 = fmaf(su[j + 2], swW[(j + 2) * 128 + col], a2);
            a3 = fmaf(su[j + 3], swW[(j + 3) * 128 + col], a3);
        }
        float v = sigmoid_fast((a0 + a1) + (a2 + a3));
        sd[col] = v;
        duoB[col] = v;
    }
    __syncthreads();

    // stage WdT rows 0..127 linear (down-ctx half)
    for (int i = tid; i < 32768 / 4; i += NTHR)
        ((float4*)swW)[i] = ((const float4*)g_WdT)[i];
    __syncthreads();

    // downward levels 0..2
    for (int k = 0; k <= 2; ++k) {
        int p0 = (1 << k) - 1, P = 1 << k;
        int col = tid;
        for (int pi = 0; pi < P; ++pi) {
            int p = p0 + pi;
            const float* dctx = &sd[p * 128];
            const float* uctx = &su[p * 128];
            float a0 = bd[col], a1 = 0.f, a2 = 0.f, a3 = 0.f;
#pragma unroll 8
            for (int j = 0; j < 128; j += 4) {
                a0 = fmaf(dctx[j + 0], swW[(j + 0) * 256 + col], a0);
                a1 = fmaf(dctx[j + 1], swW[(j + 1) * 256 + col], a1);
                a2 = fmaf(dctx[j + 2], swW[(j + 2) * 256 + col], a2);
                a3 = fmaf(dctx[j + 3], swW[(j + 3) * 256 + col], a3);
            }
#pragma unroll 8
            for (int j = 0; j < 128; j += 4) {
                a0 = fmaf(uctx[j + 0], g_WdT[(128 + j + 0) * 256 + col], a0);
                a1 = fmaf(uctx[j + 1], g_WdT[(128 + j + 1) * 256 + col], a1);
                a2 = fmaf(uctx[j + 2], g_WdT[(128 + j + 2) * 256 + col], a2);
                a3 = fmaf(uctx[j + 3], g_WdT[(128 + j + 3) * 256 + col], a3);
            }
            float v = tanh_fast((a0 + a1) + (a2 + a3));
            int child = 2 * p + 1 + (col >> 7);
            int cc = col & 127;
            sd[child * 128 + cc] = v;
            duoB[child * 256 + cc] = v;
        }
        __syncthreads();
    }
}

// ---------- the whole model, one launch ----------
__global__ __launch_bounds__(NTHR) void kall(const int* __restrict__ x,
                                             const int* __restrict__ cue,
                                             const float* __restrict__ emb,
                                             const float* __restrict__ Wc,
                                             const float* __restrict__ bc,
                                             const float* __restrict__ Wd,
                                             const float* __restrict__ bd,
                                             const float* __restrict__ Wg,
                                             const float* __restrict__ bg,
                                             const float* __restrict__ Wcl,
                                             const float* __restrict__ bcl,
                                             float* __restrict__ out) {
    extern __shared__ float smem[];
    float* swW = smem;                  // 256*WPITCH floats
    float* swAT = smem + 256 * WPITCH;  // 256*ATP floats (A^T; aliases su/sd during top)
    float* su = swAT;
    float* sd = swAT + 31 * 128;
    unsigned ls = 0;
    const int tid = threadIdx.x;
    const int gt = blockIdx.x * NTHR + tid;
    const int gstride = NBLK * NTHR;

    // ---- P0: leaf features + weight transposes ----
    for (int t = gt; t < BB * LL * 128; t += gstride) {
        int i = t & 127;
        int l = (t >> 7) & (LL - 1);
        int b = t >> 16;
        int node = (LL - 1) + l;
        float v;
        if (i < EE) v = emb[(long long)x[b * NN + node] * EE + i];
        else        v = (cue[b * NN + node] == (i - EE)) ? 1.0f : 0.0f;
        g_leaf[t] = v;
        g_duo[(b * NN + node) * 256 + 128 + i] = 0.0f;
    }
    for (int idx = gt; idx < 256 * 128; idx += gstride) {
        int j = idx >> 7, i = idx & 127;
        g_WcT[idx] = Wc[i * 256 + j];
    }
    for (int idx = gt; idx < 256 * 256; idx += gstride) {
        int j = idx >> 8, i = idx & 255;
        g_WdT[idx] = Wd[i * 256 + j];
    }
    for (int idx = gt; idx < 128 * 128; idx += gstride) {
        int j = idx >> 7, i = idx & 127;
        g_WgT[idx] = Wg[i * 128 + j];
    }
    gridbar(ls);                                        // 1

    // ---- up phase: WcT resident in smem ----
    load_w_gemm(swW, g_WcT, 128, 0);
    __syncthreads();
    level_gemm<0>(swW, swAT, bc, 8, 255, 0); gridbar(ls);   // 2
    level_gemm<1>(swW, swAT, bc, 7, 127, 0); gridbar(ls);   // 3
    level_gemm<1>(swW, swAT, bc, 6, 63, 0);  gridbar(ls);   // 4
    level_gemm<1>(swW, swAT, bc, 5, 31, 0);  gridbar(ls);   // 5
    level_gemm<1>(swW, swAT, bc, 4, 15, 0);  gridbar(ls);   // 6

    // ---- top of tree on blocks 116..147; others preload their WdT slice ----
    const int y = blockIdx.x & 1;
    if (blockIdx.x >= NBLK - BB) {
        top_tree(swW, su, sd, blockIdx.x - (NBLK - BB), bc, bd, bg);
        __syncthreads();
        load_w_gemm(swW, g_WdT, 256, y << 7);
    } else {
        load_w_gemm(swW, g_WdT, 256, y << 7);
    }
    gridbar(ls);                                        // 7

    // ---- down phase: WdT slice resident in smem ----
    level_gemm<2>(swW, swAT, bd, 3, 7, y);   gridbar(ls);   // 8
    level_gemm<2>(swW, swAT, bd, 4, 15, y);  gridbar(ls);   // 9
    level_gemm<2>(swW, swAT, bd, 5, 31, y);  gridbar(ls);   // 10
    level_gemm<2>(swW, swAT, bd, 6, 63, y);  gridbar(ls);   // 11
    level_gemm<2>(swW, swAT, bd, 7, 127, y); gridbar(ls);   // 12
    level_gemm<2>(swW, swAT, bd, 8, 255, y); gridbar(ls);   // 13

    // ---- classifier + softmax: one warp per node, strided ----
    {
        int lane = tid & 31;
        int warp0 = blockIdx.x * (NTHR / 32) + (tid >> 5);
        for (int node = warp0; node < BB * NN; node += NBLK * (NTHR / 32)) {
            const float* row = g_duo + (long long)node * 256;
            float s0 = 0.f, s1 = 0.f;
#pragma unroll
            for (int h = 0; h < 2; ++h) {
                float4 v = *(const float4*)&row[lane * 8 + h * 4];
                float4 a = *(const float4*)&Wcl[lane * 8 + h * 4];
                float4 c = *(const float4*)&Wcl[256 + lane * 8 + h * 4];
                s0 += v.x * a.x + v.y * a.y + v.z * a.z + v.w * a.w;
                s1 += v.x * c.x + v.y * c.y + v.z * c.z + v.w * c.w;
            }
#pragma unroll
            for (int o = 16; o; o >>= 1) {
                s0 += __shfl_xor_sync(0xFFFFFFFFu, s0, o);
                s1 += __shfl_xor_sync(0xFFFFFFFFu, s1, o);
            }
            if (lane == 0) {
                s0 = sigmoid_fast(s0 + bcl[0]);
                s1 = sigmoid_fast(s1 + bcl[1]);
                float e0 = __expf(s0), e1 = __expf(s1);
                float inv = __fdividef(1.0f, e0 + e1);
                out[node * 2 + 0] = e0 * inv;
                out[node * 2 + 1] = e1 * inv;
            }
        }
    }
    gridbar(ls);                                        // 14 (even count -> g_sense back to 0)
}

extern "C" void kernel_launch(void* const* d_in, const int* in_sizes, int n_in,
                              void* d_out, int out_size) {
    const int*   x    = (const int*)d_in[0];
    const int*   cue  = (const int*)d_in[2];
    const float* emb  = (const float*)d_in[4];
    const float* Wc   = (const float*)d_in[5];
    const float* bc   = (const float*)d_in[6];
    const float* Wd   = (const float*)d_in[7];
    const float* bd   = (const float*)d_in[8];
    const float* Wg   = (const float*)d_in[9];
    const float* bg   = (const float*)d_in[10];
    const float* Wcl  = (const float*)d_in[11];
    const float* bcl  = (const float*)d_in[12];
    float* out = (float*)d_out;

    static int s_attr_done = 0;
    if (!s_attr_done) {
        cudaFuncSetAttribute(kall, cudaFuncAttributeMaxDynamicSharedMemorySize, SMEM_BYTES);
        s_attr_done = 1;
    }

    kall<<<NBLK, NTHR, SMEM_BYTES>>>(x, cue, emb, Wc, bc, Wd, bd, Wg, bg, Wcl, bcl, out);
}

// round 17
// speedup vs baseline: 1.1665x; 1.1665x over previous
#include <cuda_runtime.h>
#include <math.h>

#define BB 32
#define LL 512
#define NN 1023
#define EE 126
#define NBLK 296
#define NTHR 256
#define KC 32
#define WP 140
#define AP64 68
#define SMEM_FLOATS (2 * KC * WP + 2 * KC * AP64)
#define SMEM_BYTES (SMEM_FLOATS * 4)

// Scratch (device globals — no allocations allowed)
__device__ float g_duo[BB * NN * 256];   // [b][node][0:128 down | 128:256 up]
__device__ float g_leaf[BB * LL * 128];  // leaf input features
__device__ float g_WcT[256 * 128];       // WcT[j][i] = Wc[i][j]
__device__ float g_WdT[256 * 256];
__device__ float g_WgT[128 * 128];
__device__ unsigned g_count = 0;
__device__ unsigned g_sense = 0;

// ---------- f32x2 helpers ----------
__device__ __forceinline__ unsigned long long pk2(float lo, float hi) {
    unsigned long long r;
    asm("mov.b64 %0, {%1,%2};" : "=l"(r) : "f"(lo), "f"(hi));
    return r;
}
__device__ __forceinline__ void fma2(unsigned long long& d, unsigned long long a, unsigned long long b) {
    asm("fma.rn.f32x2 %0, %1, %2, %0;" : "+l"(d) : "l"(a), "l"(b));
}
__device__ __forceinline__ void unpk2(unsigned long long v, float& a, float& b) {
    asm("mov.b64 {%0,%1}, %2;" : "=f"(a), "=f"(b) : "l"(v));
}
__device__ __forceinline__ float tanh_fast(float x) {
    float e = __expf(2.0f * x);
    return 1.0f - __fdividef(2.0f, e + 1.0f);
}
__device__ __forceinline__ float sigmoid_fast(float x) {
    return __fdividef(1.0f, 1.0f + __expf(-x));
}

// ---------- grid barrier: atomic arrivals, volatile-load polling ----------
__device__ __forceinline__ void gridbar(unsigned& ls) {
    ls ^= 1u;
    __syncthreads();
    if (threadIdx.x == 0) {
        __threadfence();
        if (atomicAdd(&g_count, 1u) == NBLK - 1) {
            g_count = 0u;
            atomicExch(&g_sense, ls);
        } else {
            while (*(volatile unsigned*)&g_sense != ls) __nanosleep(64);
            __threadfence();
        }
    }
    __syncthreads();
}

// ---------- chunked, cp.async double-buffered GEMM tile ----------
// Tile: RT rows x 128 cols, K=256 in 8 chunks of KC=32. TR=RT/16 rows/thread.
// MODE 0: up d=8 (A from g_leaf); MODE 1: up (A concat children up); MODE 2: down (A duo row)
template <int MODE, int RT>
__device__ void gemm_tile(float* smem, const float* __restrict__ WT, int Ntot, int colBase,
                          int rowBase, int logR, int off, int y, const float* __restrict__ bias) {
    constexpr int TR = RT / 16;
    constexpr int AP = RT + 4;
    constexpr int NL = RT / 32;            // float4 A-loads per thread per chunk
    float* swW = smem;                     // [2][KC][WP]
    float* saT = smem + 2 * KC * WP;       // [2][KC][AP]
    const int tid = threadIdx.x;
    const int Rm1 = (1 << logR) - 1;

    // A loader precompute
    const float* abase[NL];
    int lr[NL], lkq[NL];
#pragma unroll
    for (int j = 0; j < NL; j++) {
        int i = tid + j * NTHR;
        lr[j] = i & (RT - 1);
        lkq[j] = (i / RT) << 2;
        int m = rowBase + lr[j];
        int b = m >> logR, pi = m & Rm1;
        if (MODE == 0)      abase[j] = g_leaf + (((b << 9) + (pi << 1)) << 7);
        else if (MODE == 1) abase[j] = g_duo + (b * NN + 2 * (off + pi) + 1) * 256 + 128;
        else                abase[j] = g_duo + (b * NN + (off + pi)) * 256;
    }
    unsigned swbase = (unsigned)__cvta_generic_to_shared(swW);
    float4 av[NL];

#define ISSUE_W(CH, BUF)                                                                   \
    {                                                                                      \
        _Pragma("unroll")                                                                  \
        for (int i2 = 0; i2 < 4; i2++) {                                                   \
            int f = tid + i2 * NTHR;                                                       \
            int kk = f >> 5, c4 = f & 31;                                                  \
            const float* src = WT + ((CH) * KC + kk) * Ntot + colBase + c4 * 4;            \
            unsigned dst = swbase + ((BUF) * KC * WP + kk * WP + (c4 + (c4 >> 3)) * 4) * 4;\
            asm volatile("cp.async.cg.shared.global [%0], [%1], 16;" ::"r"(dst), "l"(src));\
        }                                                                                  \
        asm volatile("cp.async.commit_group;");                                            \
    }
#define LDG_A(CH)                                                                          \
    {                                                                                      \
        _Pragma("unroll")                                                                  \
        for (int j = 0; j < NL; j++) {                                                     \
            int gk = (CH) * KC + lkq[j];                                                   \
            int extra = (MODE == 1) ? ((gk >> 7) << 7) : 0;                                \
            av[j] = *(const float4*)(abase[j] + gk + extra);                               \
        }                                                                                  \
    }
#define STS_A(BUF)                                                                         \
    {                                                                                      \
        _Pragma("unroll")                                                                  \
        for (int j = 0; j < NL; j++) {                                                     \
            float* d = saT + (BUF) * KC * AP + lkq[j] * AP + lr[j];                        \
            d[0 * AP] = av[j].x; d[1 * AP] = av[j].y;                                      \
            d[2 * AP] = av[j].z; d[3 * AP] = av[j].w;                                      \
        }                                                                                  \
    }

    const int cg = tid & 15;
    const int rg = tid >> 4;
    const int p0 = ((2 * cg) + ((2 * cg) >> 3)) * 4;
    const int p1 = ((2 * cg + 1) + ((2 * cg + 1) >> 3)) * 4;

    unsigned long long acc[TR][4];
#pragma unroll
    for (int r = 0; r < TR; r++)
#pragma unroll
        for (int c = 0; c < 4; c++) acc[r][c] = 0ULL;

    ISSUE_W(0, 0);
    LDG_A(0);
    STS_A(0);
    asm volatile("cp.async.wait_group 0;");
    __syncthreads();

#pragma unroll 1
    for (int ch = 0; ch < 8; ch++) {
        int cur = ch & 1;
        if (ch < 7) {
            ISSUE_W(ch + 1, cur ^ 1);
            LDG_A(ch + 1);
        }
        const float* aP = saT + cur * KC * AP + rg * TR;
        const float* wP = swW + cur * KC * WP;
#pragma unroll
        for (int kk = 0; kk < KC; kk++) {
            ulonglong2 w0 = *(const ulonglong2*)(wP + kk * WP + p0);
            ulonglong2 w1 = *(const ulonglong2*)(wP + kk * WP + p1);
            unsigned long long q;
            if (TR == 4) {
                float4 a = *(const float4*)(aP + kk * AP);
                q = pk2(a.x, a.x); fma2(acc[0][0], q, w0.x); fma2(acc[0][1], q, w0.y); fma2(acc[0][2], q, w1.x); fma2(acc[0][3], q, w1.y);
                q = pk2(a.y, a.y); fma2(acc[1][0], q, w0.x); fma2(acc[1][1], q, w0.y); fma2(acc[1][2], q, w1.x); fma2(acc[1][3], q, w1.y);
                q = pk2(a.z, a.z); fma2(acc[2][0], q, w0.x); fma2(acc[2][1], q, w0.y); fma2(acc[2][2], q, w1.x); fma2(acc[2][3], q, w1.y);
                q = pk2(a.w, a.w); fma2(acc[3][0], q, w0.x); fma2(acc[3][1], q, w0.y); fma2(acc[3][2], q, w1.x); fma2(acc[3][3], q, w1.y);
            } else {
                float2 a = *(const float2*)(aP + kk * AP);
                q = pk2(a.x, a.x); fma2(acc[0][0], q, w0.x); fma2(acc[0][1], q, w0.y); fma2(acc[0][2], q, w1.x); fma2(acc[0][3], q, w1.y);
                q = pk2(a.y, a.y); fma2(acc[1][0], q, w0.x); fma2(acc[1][1], q, w0.y); fma2(acc[1][2], q, w1.x); fma2(acc[1][3], q, w1.y);
            }
        }
        if (ch < 7) {
            STS_A(cur ^ 1);
            asm volatile("cp.async.wait_group 0;");
        }
        __syncthreads();
    }
#undef ISSUE_W
#undef LDG_A
#undef STS_A

    // epilogue
    float bcol[8];
#pragma unroll
    for (int j = 0; j < 8; j++) bcol[j] = bias[colBase + cg * 8 + j];
#pragma unroll
    for (int r = 0; r < TR; r++) {
        int m = rowBase + rg * TR + r;
        int b = m >> logR, pi = m & Rm1;
        float* dst;
        if (MODE == 2) dst = g_duo + (b * NN + 2 * (off + pi) + 1 + y) * 256;
        else           dst = g_duo + (b * NN + (off + pi)) * 256 + 128;
        float o[8];
#pragma unroll
        for (int c2 = 0; c2 < 4; c2++) {
            float v0, v1;
            unpk2(acc[r][c2], v0, v1);
            o[2 * c2]     = tanh_fast(v0 + bcol[2 * c2]);
            o[2 * c2 + 1] = tanh_fast(v1 + bcol[2 * c2 + 1]);
        }
        *(float4*)&dst[cg * 8]     = make_float4(o[0], o[1], o[2], o[3]);
        *(float4*)&dst[cg * 8 + 4] = make_float4(o[4], o[5], o[6], o[7]);
    }
}

template <int MODE, int RT>
__device__ void level_gemm(float* smem, const float* __restrict__ WT, int Ntot,
                           const float* __restrict__ bias, int logR, int off, int y) {
    int mt0, stride;
    if (MODE == 2) { mt0 = blockIdx.x >> 1; stride = NBLK / 2; }
    else           { mt0 = blockIdx.x;      stride = NBLK; }
    const int colBase = (MODE == 2) ? (y << 7) : 0;
    int nmt = (BB << logR) / RT;
    for (int mt = mt0; mt < nmt; mt += stride)
        gemm_tile<MODE, RT>(smem, WT, Ntot, colBase, mt * RT, logR, off, y, bias);
}

// ---------- top of tree: up 3..0, gate, down 0..2 (L1-cached global weights) ----------
__device__ void top_tree(float* su, float* sd, int b, const float* __restrict__ bc,
                         const float* __restrict__ bd, const float* __restrict__ bg) {
    int tid = threadIdx.x;
    float* duoB = g_duo + (long long)b * NN * 256;

    for (int idx = tid; idx < 16 * 128; idx += NTHR) {
        int n = 15 + (idx >> 7), c = idx & 127;
        su[n * 128 + c] = duoB[n * 256 + 128 + c];
    }
    __syncthreads();

    for (int k = 3; k >= 0; --k) {
        int p0 = (1 << k) - 1, P = 1 << k;
        int col = tid & 127;
        for (int pi = tid >> 7; pi < P; pi += 2) {
            int p = p0 + pi;
            const float* ctx = &su[(2 * p + 1) * 128];
            float a0 = bc[col], a1 = 0.f, a2 = 0.f, a3 = 0.f;
#pragma unroll 8
            for (int j = 0; j < 256; j += 4) {
                a0 = fmaf(ctx[j + 0], g_WcT[(j + 0) * 128 + col], a0);
                a1 = fmaf(ctx[j + 1], g_WcT[(j + 1) * 128 + col], a1);
                a2 = fmaf(ctx[j + 2], g_WcT[(j + 2) * 128 + col], a2);
                a3 = fmaf(ctx[j + 3], g_WcT[(j + 3) * 128 + col], a3);
            }
            float v = tanh_fast((a0 + a1) + (a2 + a3));
            su[p * 128 + col] = v;
            duoB[p * 256 + 128 + col] = v;
        }
        __syncthreads();
    }

    if (tid < 128) {
        int col = tid;
        float a0 = bg[col], a1 = 0.f, a2 = 0.f, a3 = 0.f;
#pragma unroll 8
        for (int j = 0; j < 128; j += 4) {
            a0 = fmaf(su[j + 0], g_WgT[(j + 0) * 128 + col], a0);
            a1 = fmaf(su[j + 1], g_WgT[(j + 1) * 128 + col], a1);
            a2 = fmaf(su[j + 2], g_WgT[(j + 2) * 128 + col], a2);
            a3 = fmaf(su[j + 3], g_WgT[(j + 3) * 128 + col], a3);
        }
        float v = sigmoid_fast((a0 + a1) + (a2 + a3));
        sd[col] = v;
        duoB[col] = v;
    }
    __syncthreads();

    for (int k = 0; k <= 2; ++k) {
        int p0 = (1 << k) - 1, P = 1 << k;
        int col = tid;
        for (int pi = 0; pi < P; ++pi) {
            int p = p0 + pi;
            const float* dctx = &sd[p * 128];
            const float* uctx = &su[p * 128];
            float a0 = bd[col], a1 = 0.f, a2 = 0.f, a3 = 0.f;
#pragma unroll 8
            for (int j = 0; j < 128; j += 4) {
                a0 = fmaf(dctx[j + 0], g_WdT[(j + 0) * 256 + col], a0);
                a1 = fmaf(dctx[j + 1], g_WdT[(j + 1) * 256 + col], a1);
                a2 = fmaf(dctx[j + 2], g_WdT[(j + 2) * 256 + col], a2);
                a3 = fmaf(dctx[j + 3], g_WdT[(j + 3) * 256 + col], a3);
            }
#pragma unroll 8
            for (int j = 0; j < 128; j += 4) {
                a0 = fmaf(uctx[j + 0], g_WdT[(128 + j + 0) * 256 + col], a0);
                a1 = fmaf(uctx[j + 1], g_WdT[(128 + j + 1) * 256 + col], a1);
                a2 = fmaf(uctx[j + 2], g_WdT[(128 + j + 2) * 256 + col], a2);
                a3 = fmaf(uctx[j + 3], g_WdT[(128 + j + 3) * 256 + col], a3);
            }
            float v = tanh_fast((a0 + a1) + (a2 + a3));
            int child = 2 * p + 1 + (col >> 7);
            int cc = col & 127;
            sd[child * 128 + cc] = v;
            duoB[child * 256 + cc] = v;
        }
        __syncthreads();
    }
}

// ---------- the whole model, one launch ----------
__global__ __launch_bounds__(NTHR, 2) void kall(const int* __restrict__ x,
                                                const int* __restrict__ cue,
                                                const float* __restrict__ emb,
                                                const float* __restrict__ Wc,
                                                const float* __restrict__ bc,
                                                const float* __restrict__ Wd,
                                                const float* __restrict__ bd,
                                                const float* __restrict__ Wg,
                                                const float* __restrict__ bg,
                                                const float* __restrict__ Wcl,
                                                const float* __restrict__ bcl,
                                                float* __restrict__ out) {
    extern __shared__ float smem[];
    float* su = smem;                 // top-of-tree aliases (GEMM buffers dead then)
    float* sd = smem + 31 * 128;
    unsigned ls = 0;
    const int tid = threadIdx.x;
    const int gt = blockIdx.x * NTHR + tid;
    const int gstride = NBLK * NTHR;

    // ---- P0: leaf features + weight transposes ----
    for (int t = gt; t < BB * LL * 128; t += gstride) {
        int i = t & 127;
        int l = (t >> 7) & (LL - 1);
        int b = t >> 16;
        int node = (LL - 1) + l;
        float v;
        if (i < EE) v = emb[(long long)x[b * NN + node] * EE + i];
        else        v = (cue[b * NN + node] == (i - EE)) ? 1.0f : 0.0f;
        g_leaf[t] = v;
        g_duo[(b * NN + node) * 256 + 128 + i] = 0.0f;
    }
    for (int idx = gt; idx < 256 * 128; idx += gstride) {
        int j = idx >> 7, i = idx & 127;
        g_WcT[idx] = Wc[i * 256 + j];
    }
    for (int idx = gt; idx < 256 * 256; idx += gstride) {
        int j = idx >> 8, i = idx & 255;
        g_WdT[idx] = Wd[i * 256 + j];
    }
    for (int idx = gt; idx < 128 * 128; idx += gstride) {
        int j = idx >> 7, i = idx & 127;
        g_WgT[idx] = Wg[i * 128 + j];
    }
    gridbar(ls);                                                  // 1

    // ---- up phase ----
    level_gemm<0, 64>(smem, g_WcT, 128, bc, 8, 255, 0); gridbar(ls);  // 2
    level_gemm<1, 32>(smem, g_WcT, 128, bc, 7, 127, 0); gridbar(ls);  // 3
    level_gemm<1, 32>(smem, g_WcT, 128, bc, 6, 63, 0);  gridbar(ls);  // 4
    level_gemm<1, 32>(smem, g_WcT, 128, bc, 5, 31, 0);  gridbar(ls);  // 5
    level_gemm<1, 32>(smem, g_WcT, 128, bc, 4, 15, 0);  gridbar(ls);  // 6

    // ---- top of tree on blocks 0..31 ----
    if (blockIdx.x < BB) top_tree(su, sd, blockIdx.x, bc, bd, bg);
    gridbar(ls);                                                  // 7

    // ---- down phase ----
    const int y = blockIdx.x & 1;
    level_gemm<2, 32>(smem, g_WdT, 256, bd, 3, 7, y);   gridbar(ls);  // 8
    level_gemm<2, 32>(smem, g_WdT, 256, bd, 4, 15, y);  gridbar(ls);  // 9
    level_gemm<2, 32>(smem, g_WdT, 256, bd, 5, 31, y);  gridbar(ls);  // 10
    level_gemm<2, 32>(smem, g_WdT, 256, bd, 6, 63, y);  gridbar(ls);  // 11
    level_gemm<2, 32>(smem, g_WdT, 256, bd, 7, 127, y); gridbar(ls);  // 12
    level_gemm<2, 64>(smem, g_WdT, 256, bd, 8, 255, y); gridbar(ls);  // 13

    // ---- classifier + softmax: one warp per node, strided ----
    {
        int lane = tid & 31;
        int warp0 = blockIdx.x * (NTHR / 32) + (tid >> 5);
        for (int node = warp0; node < BB * NN; node += NBLK * (NTHR / 32)) {
            const float* row = g_duo + (long long)node * 256;
            float s0 = 0.f, s1 = 0.f;
#pragma unroll
            for (int h = 0; h < 2; ++h) {
                float4 v = *(const float4*)&row[lane * 8 + h * 4];
                float4 a = *(const float4*)&Wcl[lane * 8 + h * 4];
                float4 c = *(const float4*)&Wcl[256 + lane * 8 + h * 4];
                s0 += v.x * a.x + v.y * a.y + v.z * a.z + v.w * a.w;
                s1 += v.x * c.x + v.y * c.y + v.z * c.z + v.w * c.w;
            }
#pragma unroll
            for (int o = 16; o; o >>= 1) {
                s0 += __shfl_xor_sync(0xFFFFFFFFu, s0, o);
                s1 += __shfl_xor_sync(0xFFFFFFFFu, s1, o);
            }
            if (lane == 0) {
                s0 = sigmoid_fast(s0 + bcl[0]);
                s1 = sigmoid_fast(s1 + bcl[1]);
                float e0 = __expf(s0), e1 = __expf(s1);
                float inv = __fdividef(1.0f, e0 + e1);
                out[node * 2 + 0] = e0 * inv;
                out[node * 2 + 1] = e1 * inv;
            }
        }
    }
    gridbar(ls);                                                  // 14 (even -> g_sense back to 0)
}

extern "C" void kernel_launch(void* const* d_in, const int* in_sizes, int n_in,
                              void* d_out, int out_size) {
    const int*   x    = (const int*)d_in[0];
    const int*   cue  = (const int*)d_in[2];
    const float* emb  = (const float*)d_in[4];
    const float* Wc   = (const float*)d_in[5];
    const float* bc   = (const float*)d_in[6];
    const float* Wd   = (const float*)d_in[7];
    const float* bd   = (const float*)d_in[8];
    const float* Wg   = (const float*)d_in[9];
    const float* bg   = (const float*)d_in[10];
    const float* Wcl  = (const float*)d_in[11];
    const float* bcl  = (const float*)d_in[12];
    float* out = (float*)d_out;

    static int s_attr_done = 0;
    if (!s_attr_done) {
        cudaFuncSetAttribute(kall, cudaFuncAttributeMaxDynamicSharedMemorySize, SMEM_BYTES);
        s_attr_done = 1;
    }

    kall<<<NBLK, NTHR, SMEM_BYTES>>>(x, cue, emb, Wc, bc, Wd, bd, Wg, bg, Wcl, bcl, out);
}